// round 15
// baseline (speedup 1.0000x reference)
#include <cuda_runtime.h>
#include <math.h>

// Problem constants (fixed by the reference)
#define H_   8
#define S_   2048
#define D_   64
#define BM   64          // query rows per CTA
#define BN   64          // key cols per KV block
#define NT   256         // threads per CTA (16x16 thread grid, 4x4 micro-tiles)
#define KST  (BN + 4)    // padded row stride for the transposed-K / P buffer

__global__ void __launch_bounds__(NT, 2) fa_fp32_kernel(
    const float* __restrict__ Q,
    const float* __restrict__ K,
    const float* __restrict__ V,
    const int*   __restrict__ lens,
    float*       __restrict__ Out)
{
    extern __shared__ float smem[];
    float* sQ  = smem;                  // [BM][D_]   4096 floats (Q pre-scaled)
    float* sV  = smem + BM * D_;        // [BN][D_]   4096 floats
    float* sKT = smem + 2 * BM * D_;    // [D_][KST]  4352 floats; reused as P [BM][KST]

    const int nq    = S_ / BM;          // 32 q-tiles per (b,h)
    const int bid   = blockIdx.x;
    const int qtile = bid % nq;
    const int bh    = bid / nq;
    const int b     = bh / H_;
    const int len   = lens[b];          // >= 1 always

    const float* Qb = Q   + (size_t)bh * S_ * D_ + (size_t)(qtile * BM) * D_;
    const float* Kb = K   + (size_t)bh * S_ * D_;
    const float* Vb = V   + (size_t)bh * S_ * D_;
    float*       Ob = Out + (size_t)bh * S_ * D_ + (size_t)(qtile * BM) * D_;

    const int tid = threadIdx.x;
    const int tx  = tid & 15;           // key-col / out-dim tile index
    const int ty  = tid >> 4;           // q-row tile index
    const int r0  = ty << 2;            // 4 query rows
    const int c0  = tx << 2;            // 4 key cols (QK phase) / 4 dims (PV phase)

    const float scale = 0.044194173824159216f;  // 1/sqrt(512)

    // ---- load Q tile once, pre-scaled (coalesced float4) ----
    {
        const float4* Qg  = (const float4*)Qb;
        float4*       sQ4 = (float4*)sQ;
        #pragma unroll
        for (int k = 0; k < 4; k++) {
            int idx = tid + k * NT;     // 0..1023 float4s, row = idx>>4, col4 = idx&15
            float4 v = Qg[idx];
            v.x *= scale; v.y *= scale; v.z *= scale; v.w *= scale;
            sQ4[idx] = v;
        }
    }

    float acc[4][4];                    // O accumulator: 4 rows x 4 dims
    float m_i[4], l_i[4];
    #pragma unroll
    for (int i = 0; i < 4; i++) {
        m_i[i] = -1e30f; l_i[i] = 0.f;
        #pragma unroll
        for (int j = 0; j < 4; j++) acc[i][j] = 0.f;
    }

    // masked keys (pos >= len) get weight exactly 0 in fp32 -> skip their blocks
    const int nkb = (len + BN - 1) / BN;

    for (int kb = 0; kb < nkb; kb++) {
        const int kbase = kb * BN;
        __syncthreads();   // previous P/V consumers done before overwriting sKT/sV

        // ---- load K (transposed into sKT) and V (row-major) ----
        {
            const float4* Kg  = (const float4*)(Kb + (size_t)kbase * D_);
            const float4* Vg  = (const float4*)(Vb + (size_t)kbase * D_);
            float4*       sV4 = (float4*)sV;
            #pragma unroll
            for (int k = 0; k < 4; k++) {
                int idx = tid + k * NT;
                int key = idx >> 4;
                int d4  = (idx & 15) << 2;
                float4 kv = Kg[idx];
                sKT[(d4 + 0) * KST + key] = kv.x;
                sKT[(d4 + 1) * KST + key] = kv.y;
                sKT[(d4 + 2) * KST + key] = kv.z;
                sKT[(d4 + 3) * KST + key] = kv.w;
                sV4[idx] = Vg[idx];
            }
        }
        __syncthreads();

        // ---- S = (Q*scale) @ K^T   (4x4 per thread, float4 LDS only) ----
        float s[4][4];
        #pragma unroll
        for (int i = 0; i < 4; i++)
            #pragma unroll
            for (int j = 0; j < 4; j++) s[i][j] = 0.f;

        #pragma unroll 4
        for (int d = 0; d < D_; d += 4) {
            float qa[4][4];
            #pragma unroll
            for (int i = 0; i < 4; i++) {
                float4 t = *(const float4*)&sQ[(r0 + i) * D_ + d];
                qa[i][0] = t.x; qa[i][1] = t.y; qa[i][2] = t.z; qa[i][3] = t.w;
            }
            #pragma unroll
            for (int dd = 0; dd < 4; dd++) {
                float4 k4 = *(const float4*)&sKT[(d + dd) * KST + c0];
                #pragma unroll
                for (int i = 0; i < 4; i++) {
                    s[i][0] = fmaf(qa[i][dd], k4.x, s[i][0]);
                    s[i][1] = fmaf(qa[i][dd], k4.y, s[i][1]);
                    s[i][2] = fmaf(qa[i][dd], k4.z, s[i][2]);
                    s[i][3] = fmaf(qa[i][dd], k4.w, s[i][3]);
                }
            }
        }

        // ---- mask the tail of the last block ----
        const int rem = len - kbase;    // > 0
        if (rem < BN) {
            #pragma unroll
            for (int j = 0; j < 4; j++) {
                if (c0 + j >= rem) {
                    #pragma unroll
                    for (int i = 0; i < 4; i++) s[i][j] = -1e30f;
                }
            }
        }

        // ---- online softmax (row reductions over the 16 tx lanes) ----
        float p[4][4];
        float alpha[4];
        #pragma unroll
        for (int i = 0; i < 4; i++) {
            float v = fmaxf(fmaxf(s[i][0], s[i][1]), fmaxf(s[i][2], s[i][3]));
            v = fmaxf(v, __shfl_xor_sync(0xffffffffu, v, 1, 16));
            v = fmaxf(v, __shfl_xor_sync(0xffffffffu, v, 2, 16));
            v = fmaxf(v, __shfl_xor_sync(0xffffffffu, v, 4, 16));
            v = fmaxf(v, __shfl_xor_sync(0xffffffffu, v, 8, 16));

            float mnew = fmaxf(m_i[i], v);
            alpha[i] = __expf(m_i[i] - mnew);   // 0 on first block (m=-1e30)
            m_i[i] = mnew;

            float sum = 0.f;
            #pragma unroll
            for (int j = 0; j < 4; j++) {
                float e = __expf(s[i][j] - mnew);  // masked: exp(-1e30) == 0
                p[i][j] = e;
                sum += e;
            }
            sum += __shfl_xor_sync(0xffffffffu, sum, 1, 16);
            sum += __shfl_xor_sync(0xffffffffu, sum, 2, 16);
            sum += __shfl_xor_sync(0xffffffffu, sum, 4, 16);
            sum += __shfl_xor_sync(0xffffffffu, sum, 8, 16);

            l_i[i] = l_i[i] * alpha[i] + sum;
            #pragma unroll
            for (int j = 0; j < 4; j++) acc[i][j] *= alpha[i];
        }

        // ---- publish P to smem (reuse sKT buffer; K reads are done) ----
        __syncthreads();
        float* sP = sKT;
        #pragma unroll
        for (int i = 0; i < 4; i++) {
            *(float4*)&sP[(r0 + i) * KST + c0] =
                make_float4(p[i][0], p[i][1], p[i][2], p[i][3]);
        }
        __syncthreads();

        // ---- acc += P @ V  (thread owns 4 rows x 4 dims at column c0) ----
        #pragma unroll 4
        for (int c = 0; c < BN; c += 4) {
            float pa[4][4];
            #pragma unroll
            for (int i = 0; i < 4; i++) {
                float4 t = *(const float4*)&sP[(r0 + i) * KST + c];
                pa[i][0] = t.x; pa[i][1] = t.y; pa[i][2] = t.z; pa[i][3] = t.w;
            }
            #pragma unroll
            for (int cc = 0; cc < 4; cc++) {
                float4 v4 = *(const float4*)&sV[(c + cc) * D_ + c0];
                #pragma unroll
                for (int i = 0; i < 4; i++) {
                    acc[i][0] = fmaf(pa[i][cc], v4.x, acc[i][0]);
                    acc[i][1] = fmaf(pa[i][cc], v4.y, acc[i][1]);
                    acc[i][2] = fmaf(pa[i][cc], v4.z, acc[i][2]);
                    acc[i][3] = fmaf(pa[i][cc], v4.w, acc[i][3]);
                }
            }
        }
    }

    // ---- normalize and store (coalesced float4) ----
    #pragma unroll
    for (int i = 0; i < 4; i++) {
        float inv = 1.0f / l_i[i];      // l > 0 (len >= 1 => >=1 valid key per row)
        *(float4*)&Ob[(r0 + i) * D_ + c0] =
            make_float4(acc[i][0] * inv, acc[i][1] * inv,
                        acc[i][2] * inv, acc[i][3] * inv);
    }
}

extern "C" void kernel_launch(void* const* d_in, const int* in_sizes, int n_in,
                              void* d_out, int out_size) {
    const float* Q    = (const float*)d_in[0];
    const float* K    = (const float*)d_in[1];
    const float* V    = (const float*)d_in[2];
    const int*   lens = (const int*)d_in[3];
    float*       O    = (float*)d_out;

    const int smem_bytes = (2 * BM * D_ + D_ * KST) * (int)sizeof(float); // 50176
    cudaFuncSetAttribute(fa_fp32_kernel,
                         cudaFuncAttributeMaxDynamicSharedMemorySize, smem_bytes);

    const int grid = (4 * H_) * (S_ / BM);  // 32 (b,h) x 32 q-tiles = 1024 CTAs
    fa_fp32_kernel<<<grid, NT, smem_bytes>>>(Q, K, V, lens, O);
}

// round 16
// speedup vs baseline: 3.1312x; 3.1312x over previous
#include <cuda_runtime.h>
#include <math.h>

// Problem constants
#define H_   8
#define S_   2048
#define D_   64
#define BM   128         // query rows per CTA (4 warps x 32 rows)
#define BN   64          // keys per KV block
#define NT   128         // 4 warps
#define QST  68          // sQ/sP row stride (floats): (4*s4+s8) conflict-free A-frag reads
#define KST  68          // sK row stride: (4*s4+s8) conflict-free B-frag reads (QK)
#define VST  72          // sV row stride: (8*s4+s8) conflict-free B-frag reads (PV)

__device__ __forceinline__ float tf32r(float f) {
    unsigned u;
    asm("cvt.rna.tf32.f32 %0, %1;" : "=r"(u) : "f"(f));
    return __uint_as_float(u);
}

__device__ __forceinline__ void mma_tf32(float c[4], const unsigned a[4], const unsigned b[2]) {
    asm volatile(
        "mma.sync.aligned.m16n8k8.row.col.f32.tf32.tf32.f32 "
        "{%0,%1,%2,%3}, {%4,%5,%6,%7}, {%8,%9}, {%0,%1,%2,%3};"
        : "+f"(c[0]), "+f"(c[1]), "+f"(c[2]), "+f"(c[3])
        : "r"(a[0]), "r"(a[1]), "r"(a[2]), "r"(a[3]), "r"(b[0]), "r"(b[1]));
}

__global__ void __launch_bounds__(NT, 2) fa_tf32_kernel(
    const float* __restrict__ Q,
    const float* __restrict__ K,
    const float* __restrict__ V,
    const int*   __restrict__ lens,
    float*       __restrict__ Out)
{
    extern __shared__ float smem[];
    float* sQ = smem;                       // [BM][QST]  tf32-rounded, pre-scaled
    float* sK = sQ + BM * QST;              // [BN][KST]  tf32-rounded
    float* sV = sK + BN * KST;              // [BN][VST]  tf32-rounded
    float* sP = sV + BN * VST;              // [BM][QST]  tf32-rounded P

    const int nq    = S_ / BM;              // 16 q-tiles per (b,h)
    const int bid   = blockIdx.x;
    const int qtile = bid % nq;
    const int bh    = bid / nq;
    const int b     = bh / H_;
    const int len   = lens[b];              // >= 1

    const float* Qb = Q   + (size_t)bh * S_ * D_ + (size_t)(qtile * BM) * D_;
    const float* Kb = K   + (size_t)bh * S_ * D_;
    const float* Vb = V   + (size_t)bh * S_ * D_;
    float*       Ob = Out + (size_t)bh * S_ * D_ + (size_t)(qtile * BM) * D_;

    const int tid  = threadIdx.x;
    const int wid  = tid >> 5;
    const int lane = tid & 31;
    const int lr   = lane >> 2;             // 0..7 (groupID)
    const int lc   = lane & 3;              // 0..3 (threadID_in_group)
    const int rbase = wid * 32;             // this warp's 32 rows: two m16 tiles

    const float scale = 0.044194173824159216f;  // 1/sqrt(512)

    // ---- stage Q once: scaled + tf32-rounded (coalesced float4) ----
    {
        const float4* Qg = (const float4*)Qb;
        #pragma unroll
        for (int k = 0; k < 16; k++) {
            int idx = tid + k * NT;          // 0..2047
            int row = idx >> 4, c4 = (idx & 15) << 2;
            float4 v = Qg[idx];
            float4 r = make_float4(tf32r(v.x * scale), tf32r(v.y * scale),
                                   tf32r(v.z * scale), tf32r(v.w * scale));
            *(float4*)&sQ[row * QST + c4] = r;
        }
    }

    float acc[2][8][4];                      // O accum: 2 row-tiles x 8 d-tiles x frag
    float m_i[2][2], l_i[2][2];               // per (row-tile, row-half)
    #pragma unroll
    for (int t = 0; t < 2; t++) {
        m_i[t][0] = m_i[t][1] = -1e30f;
        l_i[t][0] = l_i[t][1] = 0.f;
        #pragma unroll
        for (int d = 0; d < 8; d++)
            #pragma unroll
            for (int j = 0; j < 4; j++) acc[t][d][j] = 0.f;
    }

    const int nkb = (len + BN - 1) / BN;     // masked blocks contribute exactly 0 -> skip

    for (int kb = 0; kb < nkb; kb++) {
        const int kbase = kb * BN;
        __syncthreads();                     // prev iter's sK/sV readers done

        // ---- stage K, V tiles (tf32-rounded) ----
        {
            const float4* Kg = (const float4*)(Kb + (size_t)kbase * D_);
            const float4* Vg = (const float4*)(Vb + (size_t)kbase * D_);
            #pragma unroll
            for (int k = 0; k < 8; k++) {
                int idx = tid + k * NT;      // 0..1023
                int row = idx >> 4, c4 = (idx & 15) << 2;
                float4 kv = Kg[idx];
                float4 vv = Vg[idx];
                *(float4*)&sK[row * KST + c4] =
                    make_float4(tf32r(kv.x), tf32r(kv.y), tf32r(kv.z), tf32r(kv.w));
                *(float4*)&sV[row * VST + c4] =
                    make_float4(tf32r(vv.x), tf32r(vv.y), tf32r(vv.z), tf32r(vv.w));
            }
        }
        __syncthreads();

        // ---- S = Q @ K^T : per warp 32 rows x 64 cols via m16n8k8 ----
        float sf[2][8][4];
        #pragma unroll
        for (int t = 0; t < 2; t++)
            #pragma unroll
            for (int n = 0; n < 8; n++)
                #pragma unroll
                for (int j = 0; j < 4; j++) sf[t][n][j] = 0.f;

        #pragma unroll
        for (int k0 = 0; k0 < D_; k0 += 8) {
            unsigned a[2][4];
            #pragma unroll
            for (int t = 0; t < 2; t++) {
                int r = rbase + t * 16 + lr;
                a[t][0] = __float_as_uint(sQ[r       * QST + k0     + lc]);
                a[t][1] = __float_as_uint(sQ[(r + 8) * QST + k0     + lc]);
                a[t][2] = __float_as_uint(sQ[r       * QST + k0 + 4 + lc]);
                a[t][3] = __float_as_uint(sQ[(r + 8) * QST + k0 + 4 + lc]);
            }
            #pragma unroll
            for (int n = 0; n < 8; n++) {
                unsigned bf[2];
                bf[0] = __float_as_uint(sK[(n * 8 + lr) * KST + k0     + lc]);
                bf[1] = __float_as_uint(sK[(n * 8 + lr) * KST + k0 + 4 + lc]);
                mma_tf32(sf[0][n], a[0], bf);
                mma_tf32(sf[1][n], a[1], bf);
            }
        }

        // ---- tail mask ----
        const int rem = len - kbase;         // > 0
        if (rem < BN) {
            #pragma unroll
            for (int n = 0; n < 8; n++) {
                int c = n * 8 + 2 * lc;
                if (c >= rem)     { sf[0][n][0] = -1e30f; sf[0][n][2] = -1e30f;
                                    sf[1][n][0] = -1e30f; sf[1][n][2] = -1e30f; }
                if (c + 1 >= rem) { sf[0][n][1] = -1e30f; sf[0][n][3] = -1e30f;
                                    sf[1][n][1] = -1e30f; sf[1][n][3] = -1e30f; }
            }
        }

        // ---- online softmax (rows: frag halves h=0 -> lanes lr, h=1 -> lr+8) ----
        #pragma unroll
        for (int t = 0; t < 2; t++) {
            #pragma unroll
            for (int h = 0; h < 2; h++) {
                float vmax = -1e30f;
                #pragma unroll
                for (int n = 0; n < 8; n++)
                    vmax = fmaxf(vmax, fmaxf(sf[t][n][2*h], sf[t][n][2*h+1]));
                vmax = fmaxf(vmax, __shfl_xor_sync(0xffffffffu, vmax, 1));
                vmax = fmaxf(vmax, __shfl_xor_sync(0xffffffffu, vmax, 2));

                float mo = m_i[t][h];
                float mn = fmaxf(mo, vmax);
                float alpha = __expf(mo - mn);
                m_i[t][h] = mn;

                float sum = 0.f;
                #pragma unroll
                for (int n = 0; n < 8; n++) {
                    float p0 = __expf(sf[t][n][2*h]     - mn);
                    float p1 = __expf(sf[t][n][2*h + 1] - mn);
                    sf[t][n][2*h]     = p0;
                    sf[t][n][2*h + 1] = p1;
                    sum += p0 + p1;
                }
                sum += __shfl_xor_sync(0xffffffffu, sum, 1);
                sum += __shfl_xor_sync(0xffffffffu, sum, 2);
                l_i[t][h] = l_i[t][h] * alpha + sum;

                #pragma unroll
                for (int d = 0; d < 8; d++) {
                    acc[t][d][2*h]     *= alpha;
                    acc[t][d][2*h + 1] *= alpha;
                }
            }
        }

        // ---- store P (tf32-rounded) to warp-private sP rows; no sync needed ----
        #pragma unroll
        for (int t = 0; t < 2; t++) {
            int r = rbase + t * 16 + lr;
            #pragma unroll
            for (int n = 0; n < 8; n++) {
                int c = n * 8 + 2 * lc;
                *(float2*)&sP[r       * QST + c] =
                    make_float2(tf32r(sf[t][n][0]), tf32r(sf[t][n][1]));
                *(float2*)&sP[(r + 8) * QST + c] =
                    make_float2(tf32r(sf[t][n][2]), tf32r(sf[t][n][3]));
            }
        }

        // ---- acc += P @ V ----
        #pragma unroll
        for (int c0 = 0; c0 < BN; c0 += 8) {
            unsigned a[2][4];
            #pragma unroll
            for (int t = 0; t < 2; t++) {
                int r = rbase + t * 16 + lr;
                a[t][0] = __float_as_uint(sP[r       * QST + c0     + lc]);
                a[t][1] = __float_as_uint(sP[(r + 8) * QST + c0     + lc]);
                a[t][2] = __float_as_uint(sP[r       * QST + c0 + 4 + lc]);
                a[t][3] = __float_as_uint(sP[(r + 8) * QST + c0 + 4 + lc]);
            }
            #pragma unroll
            for (int d = 0; d < 8; d++) {
                unsigned bf[2];
                bf[0] = __float_as_uint(sV[(c0     + lc) * VST + d * 8 + lr]);
                bf[1] = __float_as_uint(sV[(c0 + 4 + lc) * VST + d * 8 + lr]);
                mma_tf32(acc[0][d], a[0], bf);
                mma_tf32(acc[1][d], a[1], bf);
            }
        }
    }

    // ---- normalize + store (float2 per fragment pair) ----
    #pragma unroll
    for (int t = 0; t < 2; t++) {
        #pragma unroll
        for (int h = 0; h < 2; h++) {
            int r = rbase + t * 16 + lr + h * 8;
            float inv = 1.0f / l_i[t][h];
            #pragma unroll
            for (int d = 0; d < 8; d++) {
                *(float2*)&Ob[r * D_ + d * 8 + 2 * lc] =
                    make_float2(acc[t][d][2*h] * inv, acc[t][d][2*h + 1] * inv);
            }
        }
    }
}

extern "C" void kernel_launch(void* const* d_in, const int* in_sizes, int n_in,
                              void* d_out, int out_size) {
    const float* Q    = (const float*)d_in[0];
    const float* K    = (const float*)d_in[1];
    const float* V    = (const float*)d_in[2];
    const int*   lens = (const int*)d_in[3];
    float*       O    = (float*)d_out;

    const int smem_bytes = (BM * QST + BN * KST + BN * VST + BM * QST) * (int)sizeof(float); // 105472
    cudaFuncSetAttribute(fa_tf32_kernel,
                         cudaFuncAttributeMaxDynamicSharedMemorySize, smem_bytes);

    const int grid = (4 * H_) * (S_ / BM);   // 32 (b,h) x 16 q-tiles = 512 CTAs
    fa_tf32_kernel<<<grid, NT, smem_bytes>>>(Q, K, V, lens, O);
}

// round 17
// speedup vs baseline: 3.3775x; 1.0787x over previous
#include <cuda_runtime.h>
#include <math.h>

// Problem constants
#define H_   8
#define S_   2048
#define D_   64
#define BM   128         // query rows per CTA (8 warps x 16 rows)
#define BN   64          // keys per KV block
#define NT   256         // 8 warps
#define QST  68          // sQ/sP row stride (floats): conflict-free A-frag reads
#define KST  68          // sK row stride: conflict-free B-frag reads (QK)
#define VST  72          // sV row stride: conflict-free B-frag reads (PV)

__device__ __forceinline__ float tf32r(float f) {
    unsigned u;
    asm("cvt.rna.tf32.f32 %0, %1;" : "=r"(u) : "f"(f));
    return __uint_as_float(u);
}

__device__ __forceinline__ void mma_tf32(float c[4], const unsigned a[4], const unsigned b[2]) {
    asm volatile(
        "mma.sync.aligned.m16n8k8.row.col.f32.tf32.tf32.f32 "
        "{%0,%1,%2,%3}, {%4,%5,%6,%7}, {%8,%9}, {%0,%1,%2,%3};"
        : "+f"(c[0]), "+f"(c[1]), "+f"(c[2]), "+f"(c[3])
        : "r"(a[0]), "r"(a[1]), "r"(a[2]), "r"(a[3]), "r"(b[0]), "r"(b[1]));
}

__global__ void __launch_bounds__(NT, 2) fa_tf32_kernel(
    const float* __restrict__ Q,
    const float* __restrict__ K,
    const float* __restrict__ V,
    const int*   __restrict__ lens,
    float*       __restrict__ Out)
{
    extern __shared__ float smem[];
    float* sQ = smem;                       // [BM][QST]  tf32-rounded, pre-scaled
    float* sK = sQ + BM * QST;              // [BN][KST]  tf32-rounded
    float* sV = sK + BN * KST;              // [BN][VST]  tf32-rounded
    float* sP = sV + BN * VST;              // [BM][QST]  tf32-rounded P

    const int nq    = S_ / BM;              // 16 q-tiles per (b,h)
    const int bid   = blockIdx.x;
    const int qtile = bid % nq;
    const int bh    = bid / nq;
    const int b     = bh / H_;
    const int len   = lens[b];              // >= 1

    const float* Qb = Q   + (size_t)bh * S_ * D_ + (size_t)(qtile * BM) * D_;
    const float* Kb = K   + (size_t)bh * S_ * D_;
    const float* Vb = V   + (size_t)bh * S_ * D_;
    float*       Ob = Out + (size_t)bh * S_ * D_ + (size_t)(qtile * BM) * D_;

    const int tid  = threadIdx.x;
    const int wid  = tid >> 5;
    const int lane = tid & 31;
    const int lr   = lane >> 2;             // 0..7
    const int lc   = lane & 3;              // 0..3
    const int rbase = wid * 16;             // this warp's 16 rows: one m16 tile

    const float scale = 0.044194173824159216f;  // 1/sqrt(512)

    // ---- stage Q once: scaled + tf32-rounded (coalesced float4) ----
    {
        const float4* Qg = (const float4*)Qb;
        #pragma unroll
        for (int k = 0; k < 8; k++) {
            int idx = tid + k * NT;          // 0..2047
            int row = idx >> 4, c4 = (idx & 15) << 2;
            float4 v = Qg[idx];
            *(float4*)&sQ[row * QST + c4] =
                make_float4(tf32r(v.x * scale), tf32r(v.y * scale),
                            tf32r(v.z * scale), tf32r(v.w * scale));
        }
    }

    float acc[8][4];                         // O accum: 8 d-tiles x frag
    float m_i[2], l_i[2];                    // per row-half (lr, lr+8)
    m_i[0] = m_i[1] = -1e30f;
    l_i[0] = l_i[1] = 0.f;
    #pragma unroll
    for (int d = 0; d < 8; d++)
        #pragma unroll
        for (int j = 0; j < 4; j++) acc[d][j] = 0.f;

    const int nkb = (len + BN - 1) / BN;     // masked blocks contribute exactly 0 -> skip

    for (int kb = 0; kb < nkb; kb++) {
        const int kbase = kb * BN;
        __syncthreads();                     // prev iter's sK/sV readers done

        // ---- stage K, V tiles (tf32-rounded) ----
        {
            const float4* Kg = (const float4*)(Kb + (size_t)kbase * D_);
            const float4* Vg = (const float4*)(Vb + (size_t)kbase * D_);
            #pragma unroll
            for (int k = 0; k < 4; k++) {
                int idx = tid + k * NT;      // 0..1023
                int row = idx >> 4, c4 = (idx & 15) << 2;
                float4 kv = Kg[idx];
                float4 vv = Vg[idx];
                *(float4*)&sK[row * KST + c4] =
                    make_float4(tf32r(kv.x), tf32r(kv.y), tf32r(kv.z), tf32r(kv.w));
                *(float4*)&sV[row * VST + c4] =
                    make_float4(tf32r(vv.x), tf32r(vv.y), tf32r(vv.z), tf32r(vv.w));
            }
        }
        __syncthreads();

        // ---- S = Q @ K^T : per warp 16 rows x 64 cols via m16n8k8 ----
        float sf[8][4];
        #pragma unroll
        for (int n = 0; n < 8; n++)
            #pragma unroll
            for (int j = 0; j < 4; j++) sf[n][j] = 0.f;

        #pragma unroll
        for (int k0 = 0; k0 < D_; k0 += 8) {
            unsigned a[4];
            {
                int r = rbase + lr;
                a[0] = __float_as_uint(sQ[r       * QST + k0     + lc]);
                a[1] = __float_as_uint(sQ[(r + 8) * QST + k0     + lc]);
                a[2] = __float_as_uint(sQ[r       * QST + k0 + 4 + lc]);
                a[3] = __float_as_uint(sQ[(r + 8) * QST + k0 + 4 + lc]);
            }
            #pragma unroll
            for (int n = 0; n < 8; n++) {
                unsigned bf[2];
                bf[0] = __float_as_uint(sK[(n * 8 + lr) * KST + k0     + lc]);
                bf[1] = __float_as_uint(sK[(n * 8 + lr) * KST + k0 + 4 + lc]);
                mma_tf32(sf[n], a, bf);
            }
        }

        // ---- tail mask ----
        const int rem = len - kbase;         // > 0
        if (rem < BN) {
            #pragma unroll
            for (int n = 0; n < 8; n++) {
                int c = n * 8 + 2 * lc;
                if (c >= rem)     { sf[n][0] = -1e30f; sf[n][2] = -1e30f; }
                if (c + 1 >= rem) { sf[n][1] = -1e30f; sf[n][3] = -1e30f; }
            }
        }

        // ---- online softmax (row halves: h=0 -> row lr, h=1 -> row lr+8) ----
        #pragma unroll
        for (int h = 0; h < 2; h++) {
            float vmax = -1e30f;
            #pragma unroll
            for (int n = 0; n < 8; n++)
                vmax = fmaxf(vmax, fmaxf(sf[n][2*h], sf[n][2*h+1]));
            vmax = fmaxf(vmax, __shfl_xor_sync(0xffffffffu, vmax, 1));
            vmax = fmaxf(vmax, __shfl_xor_sync(0xffffffffu, vmax, 2));

            float mo = m_i[h];
            float mn = fmaxf(mo, vmax);
            float alpha = __expf(mo - mn);
            m_i[h] = mn;

            float sum = 0.f;
            #pragma unroll
            for (int n = 0; n < 8; n++) {
                float p0 = __expf(sf[n][2*h]     - mn);
                float p1 = __expf(sf[n][2*h + 1] - mn);
                sf[n][2*h]     = p0;
                sf[n][2*h + 1] = p1;
                sum += p0 + p1;
            }
            sum += __shfl_xor_sync(0xffffffffu, sum, 1);
            sum += __shfl_xor_sync(0xffffffffu, sum, 2);
            l_i[h] = l_i[h] * alpha + sum;

            #pragma unroll
            for (int d = 0; d < 8; d++) {
                acc[d][2*h]     *= alpha;
                acc[d][2*h + 1] *= alpha;
            }
        }

        // ---- store P (tf32-rounded) to warp-private sP rows; no sync needed ----
        {
            int r = rbase + lr;
            #pragma unroll
            for (int n = 0; n < 8; n++) {
                int c = n * 8 + 2 * lc;
                *(float2*)&sP[r       * QST + c] =
                    make_float2(tf32r(sf[n][0]), tf32r(sf[n][1]));
                *(float2*)&sP[(r + 8) * QST + c] =
                    make_float2(tf32r(sf[n][2]), tf32r(sf[n][3]));
            }
        }

        // ---- acc += P @ V ----
        #pragma unroll
        for (int c0 = 0; c0 < BN; c0 += 8) {
            unsigned a[4];
            {
                int r = rbase + lr;
                a[0] = __float_as_uint(sP[r       * QST + c0     + lc]);
                a[1] = __float_as_uint(sP[(r + 8) * QST + c0     + lc]);
                a[2] = __float_as_uint(sP[r       * QST + c0 + 4 + lc]);
                a[3] = __float_as_uint(sP[(r + 8) * QST + c0 + 4 + lc]);
            }
            #pragma unroll
            for (int d = 0; d < 8; d++) {
                unsigned bf[2];
                bf[0] = __float_as_uint(sV[(c0     + lc) * VST + d * 8 + lr]);
                bf[1] = __float_as_uint(sV[(c0 + 4 + lc) * VST + d * 8 + lr]);
                mma_tf32(acc[d], a, bf);
            }
        }
    }

    // ---- normalize + store (float2 per fragment pair) ----
    #pragma unroll
    for (int h = 0; h < 2; h++) {
        int r = rbase + lr + h * 8;
        float inv = 1.0f / l_i[h];
        #pragma unroll
        for (int d = 0; d < 8; d++) {
            *(float2*)&Ob[r * D_ + d * 8 + 2 * lc] =
                make_float2(acc[d][2*h] * inv, acc[d][2*h + 1] * inv);
        }
    }
}

extern "C" void kernel_launch(void* const* d_in, const int* in_sizes, int n_in,
                              void* d_out, int out_size) {
    const float* Q    = (const float*)d_in[0];
    const float* K    = (const float*)d_in[1];
    const float* V    = (const float*)d_in[2];
    const int*   lens = (const int*)d_in[3];
    float*       O    = (float*)d_out;

    const int smem_bytes = (BM * QST + BN * KST + BN * VST + BM * QST) * (int)sizeof(float); // 105472
    cudaFuncSetAttribute(fa_tf32_kernel,
                         cudaFuncAttributeMaxDynamicSharedMemorySize, smem_bytes);

    const int grid = (4 * H_) * (S_ / BM);   // 32 (b,h) x 16 q-tiles = 512 CTAs
    fa_tf32_kernel<<<grid, NT, smem_bytes>>>(Q, K, V, lens, O);
}